// round 5
// baseline (speedup 1.0000x reference)
#include <cuda_runtime.h>
#include <cuda_bf16.h>

#define Bn 8
#define Sn 2048
#define Dn 256
#define Hn 4
#define DHn 64

// ---------------- scratch (static device arrays; no allocation) ----------------
__device__ __nv_bfloat16 g_qh[Bn*Hn*Sn*DHn];  // 8 MB each: pre-split Q/K (hi/lo bf16)
__device__ __nv_bfloat16 g_ql[Bn*Hn*Sn*DHn];
__device__ __nv_bfloat16 g_kh[Bn*Hn*Sn*DHn];
__device__ __nv_bfloat16 g_kl[Bn*Hn*Sn*DHn];
__device__ float g_vs[Bn*Sn*DHn];             // 4 MB  [B,S,DH], tf32-pre-rounded
__device__ float g_heads[Bn*Hn*Sn*DHn];       // 16 MB [B,H,S,DH] (carries 1/(4*rowsum))
__device__ unsigned g_mbits[Bn*Sn*(Sn/32)];   // 16.8 MB bit-packed mask

// ---------------- helpers ----------------
__device__ __forceinline__ unsigned f2tf(float x) {
    unsigned u;
    asm("cvt.rna.tf32.f32 %0, %1;" : "=r"(u) : "f"(x));
    return u;
}
__device__ __forceinline__ float tf32r(float x) { return __uint_as_float(f2tf(x)); }
__device__ __forceinline__ void mma8(float* c, const unsigned* a, const unsigned* b) {
    asm volatile("mma.sync.aligned.m16n8k8.row.col.f32.tf32.tf32.f32 "
        "{%0,%1,%2,%3}, {%4,%5,%6,%7}, {%8,%9}, {%0,%1,%2,%3};\n"
        : "+f"(c[0]), "+f"(c[1]), "+f"(c[2]), "+f"(c[3])
        : "r"(a[0]), "r"(a[1]), "r"(a[2]), "r"(a[3]), "r"(b[0]), "r"(b[1]));
}
__device__ __forceinline__ void mma16(float* c, const unsigned* a, const unsigned* b) {
    asm volatile("mma.sync.aligned.m16n8k16.row.col.f32.bf16.bf16.f32 "
        "{%0,%1,%2,%3}, {%4,%5,%6,%7}, {%8,%9}, {%0,%1,%2,%3};\n"
        : "+f"(c[0]), "+f"(c[1]), "+f"(c[2]), "+f"(c[3])
        : "r"(a[0]), "r"(a[1]), "r"(a[2]), "r"(a[3]), "r"(b[0]), "r"(b[1]));
}
__device__ __forceinline__ void bsplit(float x, __nv_bfloat16 &hi, __nv_bfloat16 &lo) {
    hi = __float2bfloat16_rn(x);
    lo = __float2bfloat16_rn(x - __bfloat162float(hi));
}

// FMA-pipe exp(s/8): magic-constant round + degree-5 poly + exponent splice. rel err ~2e-6.
__device__ __forceinline__ float fexp8(float s) {
    const float c = 0.18033688011112042f;   // log2(e)/8
    const float MAGIC = 12582912.0f;        // 1.5 * 2^23
    float t = fmaf(s, c, MAGIC);
    float k = t - MAGIC;
    float f = fmaf(s, c, -k);               // f in [-0.5, 0.5]
    float p = 1.3333558146e-3f;
    p = fmaf(p, f, 9.6181291076e-3f);
    p = fmaf(p, f, 5.5504108665e-2f);
    p = fmaf(p, f, 2.4022650696e-1f);
    p = fmaf(p, f, 6.9314718056e-1f);
    p = fmaf(p, f, 1.0f);
    int ik = __float_as_int(t) << 23;
    return __int_as_float(__float_as_int(p) + ik);
}

// ================= Kernel 0: bit-pack the mask =================
__global__ void pack_mask_kernel(const int* __restrict__ mask) {
    size_t i = (size_t)blockIdx.x * 256 + threadIdx.x;
    int m = mask[i] != 0;
    unsigned bal = __ballot_sync(0xffffffffu, m);
    if ((threadIdx.x & 31) == 0) g_mbits[i >> 5] = bal;
}

// ================= Kernel 1: projections via bf16x3 GEMM =================
// z=0: qs = q @ Wq[h] (store bf16 hi/lo)   z=1: ks = k @ Wk[h] (store bf16 hi/lo)
// z=2: vs = v @ Wv (store tf32-rounded f32)
__global__ __launch_bounds__(256) void proj_kernel(
    const float* __restrict__ q, const float* __restrict__ k, const float* __restrict__ v,
    const float* __restrict__ Wq, const float* __restrict__ Wk, const float* __restrict__ Wv)
{
    int z = blockIdx.z;
    if (z == 2 && blockIdx.x > 0) return;
    __shared__ __nv_bfloat16 Ah[128][40];
    __shared__ __nv_bfloat16 Al[128][40];
    __shared__ __nv_bfloat16 Bh[64][40];   // stored as [n][k]
    __shared__ __nv_bfloat16 Bl[64][40];

    const float* X = (z == 0) ? q : (z == 1) ? k : v;
    const float* W = (z == 0) ? (Wq + (size_t)blockIdx.x * Dn * DHn)
                   : (z == 1) ? (Wk + (size_t)blockIdx.x * Dn * DHn) : Wv;
    int M0 = blockIdx.y * 128;
    int tid = threadIdx.x;
    int warp = tid >> 5, lane = tid & 31;
    int g = lane >> 2, t = lane & 3;
    int wm0 = (warp >> 1) * 32, wn0 = (warp & 1) * 32;

    float c[2][4][4];
    #pragma unroll
    for (int mt = 0; mt < 2; mt++)
        #pragma unroll
        for (int nt = 0; nt < 4; nt++)
            #pragma unroll
            for (int i = 0; i < 4; i++) c[mt][nt][i] = 0.f;

    for (int kc = 0; kc < 8; kc++) {
        int K0 = kc * 32;
        #pragma unroll
        for (int it = 0; it < 4; it++) {
            int i = tid + it * 256;
            int r = i >> 3, c4 = (i & 7) << 2;
            float4 val = *reinterpret_cast<const float4*>(&X[(size_t)(M0 + r) * Dn + K0 + c4]);
            __nv_bfloat16 hi, lo;
            bsplit(val.x, hi, lo); Ah[r][c4]   = hi; Al[r][c4]   = lo;
            bsplit(val.y, hi, lo); Ah[r][c4+1] = hi; Al[r][c4+1] = lo;
            bsplit(val.z, hi, lo); Ah[r][c4+2] = hi; Al[r][c4+2] = lo;
            bsplit(val.w, hi, lo); Ah[r][c4+3] = hi; Al[r][c4+3] = lo;
        }
        #pragma unroll
        for (int it = 0; it < 2; it++) {
            int i = tid + it * 256;
            int r = i >> 4, c4 = (i & 15) << 2;   // r = k row (0..31), c4 = n
            float4 val = *reinterpret_cast<const float4*>(&W[(size_t)(K0 + r) * DHn + c4]);
            __nv_bfloat16 hi, lo;
            bsplit(val.x, hi, lo); Bh[c4][r]   = hi; Bl[c4][r]   = lo;
            bsplit(val.y, hi, lo); Bh[c4+1][r] = hi; Bl[c4+1][r] = lo;
            bsplit(val.z, hi, lo); Bh[c4+2][r] = hi; Bl[c4+2][r] = lo;
            bsplit(val.w, hi, lo); Bh[c4+3][r] = hi; Bl[c4+3][r] = lo;
        }
        __syncthreads();
        #pragma unroll
        for (int kk = 0; kk < 2; kk++) {
            int k0 = kk * 16;
            unsigned ah[2][4], al[2][4], bh[4][2], bl[4][2];
            #pragma unroll
            for (int mt = 0; mt < 2; mt++) {
                int rb = wm0 + mt * 16;
                ah[mt][0] = *reinterpret_cast<const unsigned*>(&Ah[rb + g][k0 + 2*t]);
                ah[mt][1] = *reinterpret_cast<const unsigned*>(&Ah[rb + 8 + g][k0 + 2*t]);
                ah[mt][2] = *reinterpret_cast<const unsigned*>(&Ah[rb + g][k0 + 8 + 2*t]);
                ah[mt][3] = *reinterpret_cast<const unsigned*>(&Ah[rb + 8 + g][k0 + 8 + 2*t]);
                al[mt][0] = *reinterpret_cast<const unsigned*>(&Al[rb + g][k0 + 2*t]);
                al[mt][1] = *reinterpret_cast<const unsigned*>(&Al[rb + 8 + g][k0 + 2*t]);
                al[mt][2] = *reinterpret_cast<const unsigned*>(&Al[rb + g][k0 + 8 + 2*t]);
                al[mt][3] = *reinterpret_cast<const unsigned*>(&Al[rb + 8 + g][k0 + 8 + 2*t]);
            }
            #pragma unroll
            for (int nt = 0; nt < 4; nt++) {
                int cb = wn0 + nt * 8 + g;
                bh[nt][0] = *reinterpret_cast<const unsigned*>(&Bh[cb][k0 + 2*t]);
                bh[nt][1] = *reinterpret_cast<const unsigned*>(&Bh[cb][k0 + 8 + 2*t]);
                bl[nt][0] = *reinterpret_cast<const unsigned*>(&Bl[cb][k0 + 2*t]);
                bl[nt][1] = *reinterpret_cast<const unsigned*>(&Bl[cb][k0 + 8 + 2*t]);
            }
            #pragma unroll
            for (int mt = 0; mt < 2; mt++)
                #pragma unroll
                for (int nt = 0; nt < 4; nt++) {
                    mma16(c[mt][nt], ah[mt], bh[nt]);
                    mma16(c[mt][nt], ah[mt], bl[nt]);
                    mma16(c[mt][nt], al[mt], bh[nt]);
                }
        }
        __syncthreads();
    }
    #pragma unroll
    for (int mt = 0; mt < 2; mt++)
        #pragma unroll
        for (int nt = 0; nt < 4; nt++) {
            int e = wn0 + nt * 8 + 2 * t;
            #pragma unroll
            for (int half = 0; half < 2; half++) {
                int r = M0 + wm0 + mt * 16 + half * 8 + g;
                int bb = r >> 11, s = r & 2047;
                float v0 = c[mt][nt][half * 2], v1 = c[mt][nt][half * 2 + 1];
                if (z == 2) {
                    *reinterpret_cast<float2*>(&g_vs[((size_t)bb * Sn + s) * DHn + e]) =
                        make_float2(tf32r(v0), tf32r(v1));
                } else {
                    int h = blockIdx.x;
                    size_t idx = (((size_t)(bb * Hn + h)) * Sn + s) * DHn + e;
                    __nv_bfloat16 h0, l0, h1, l1;
                    bsplit(v0, h0, l0); bsplit(v1, h1, l1);
                    __nv_bfloat162 vh; vh.x = h0; vh.y = h1;
                    __nv_bfloat162 vl; vl.x = l0; vl.y = l1;
                    if (z == 0) {
                        *reinterpret_cast<__nv_bfloat162*>(&g_qh[idx]) = vh;
                        *reinterpret_cast<__nv_bfloat162*>(&g_ql[idx]) = vl;
                    } else {
                        *reinterpret_cast<__nv_bfloat162*>(&g_kh[idx]) = vh;
                        *reinterpret_cast<__nv_bfloat162*>(&g_kl[idx]) = vl;
                    }
                }
            }
        }
}

// ================= Kernel 2: fused attention (+ in-kernel normalization) ========
__global__ __launch_bounds__(256) void attn_kernel(float* __restrict__ attn_out)
{
    extern __shared__ char smraw[];
    __nv_bfloat16 (*Qh)[72] = reinterpret_cast<__nv_bfloat16(*)[72]>(smraw);            // 128x72
    __nv_bfloat16 (*Ql)[72] = reinterpret_cast<__nv_bfloat16(*)[72]>(smraw + 18432);
    __nv_bfloat16 (*Kh)[72] = reinterpret_cast<__nv_bfloat16(*)[72]>(smraw + 36864);    // 64x72
    __nv_bfloat16 (*Kl)[72] = reinterpret_cast<__nv_bfloat16(*)[72]>(smraw + 46080);
    float (*Vs)[72] = reinterpret_cast<float(*)[72]>(smraw + 55296);                    // 64x72 f32
    float (*Ps)[68] = reinterpret_cast<float(*)[68]>(smraw + 73728);                    // 128x68 f32
    unsigned (*m2)[2] = reinterpret_cast<unsigned(*)[2]>(smraw + 108544);               // 128x2
    float* rowsum = reinterpret_cast<float*>(smraw + 109568);                           // 128

    int st = blockIdx.x, h = blockIdx.y, b = blockIdx.z;
    int bh = b * Hn + h;
    int S0 = st * 128;
    int tid = threadIdx.x, warp = tid >> 5, lane = tid & 31;
    int g = lane >> 2, t = lane & 3;
    int wm0 = (warp >> 1) * 32, wn0 = (warp & 1) * 32;

    const __nv_bfloat16* qh_src = g_qh + ((size_t)bh * Sn + S0) * DHn;
    const __nv_bfloat16* ql_src = g_ql + ((size_t)bh * Sn + S0) * DHn;
    const __nv_bfloat16* kh_src = g_kh + (size_t)bh * Sn * DHn;
    const __nv_bfloat16* kl_src = g_kl + (size_t)bh * Sn * DHn;
    const float* vsrc = g_vs + (size_t)b * Sn * DHn;
    const unsigned* msrc = g_mbits + ((size_t)b * Sn + S0) * (Sn / 32);
    float* aout = attn_out + (size_t)bh * Sn * Sn;

    // stage Q hi/lo (pure copies, no cvt)
    #pragma unroll
    for (int it = 0; it < 4; it++) {
        int i = tid + it * 256;
        int r = i >> 3, c8 = (i & 7) << 3;
        *reinterpret_cast<uint4*>(&Qh[r][c8]) =
            *reinterpret_cast<const uint4*>(&qh_src[(size_t)r * DHn + c8]);
        *reinterpret_cast<uint4*>(&Ql[r][c8]) =
            *reinterpret_cast<const uint4*>(&ql_src[(size_t)r * DHn + c8]);
    }
    if (tid < 128) rowsum[tid] = 0.f;

    float cO[2][4][4];
    #pragma unroll
    for (int mt = 0; mt < 2; mt++)
        #pragma unroll
        for (int nt = 0; nt < 4; nt++)
            #pragma unroll
            for (int i = 0; i < 4; i++) cO[mt][nt][i] = 0.f;
    float rpart[2][2] = {{0.f, 0.f}, {0.f, 0.f}};

    for (int tc = 0; tc < 32; tc++) {
        int T0 = tc * 64;
        // stage K hi/lo (copies) + V (pre-rounded f32) + mask words
        #pragma unroll
        for (int it = 0; it < 2; it++) {
            int i = tid + it * 256;
            int r = i >> 3, c8 = (i & 7) << 3;
            *reinterpret_cast<uint4*>(&Kh[r][c8]) =
                *reinterpret_cast<const uint4*>(&kh_src[(size_t)(T0 + r) * DHn + c8]);
            *reinterpret_cast<uint4*>(&Kl[r][c8]) =
                *reinterpret_cast<const uint4*>(&kl_src[(size_t)(T0 + r) * DHn + c8]);
        }
        #pragma unroll
        for (int it = 0; it < 4; it++) {
            int i = tid + it * 256;
            int r = i >> 4, c4 = (i & 15) << 2;
            float4 vv = *reinterpret_cast<const float4*>(&vsrc[(size_t)(T0 + r) * DHn + c4]);
            Vs[r][c4] = vv.x; Vs[r][c4+1] = vv.y; Vs[r][c4+2] = vv.z; Vs[r][c4+3] = vv.w;
        }
        { // 128 rows x 2 mask words
            int r = tid >> 1, w = tid & 1;
            m2[r][w] = msrc[(size_t)r * (Sn / 32) + (T0 >> 5) + w];
        }
        __syncthreads();

        // ---- QK^T (bf16x3) ----
        float cS[2][4][4];
        #pragma unroll
        for (int mt = 0; mt < 2; mt++)
            #pragma unroll
            for (int nt = 0; nt < 4; nt++)
                #pragma unroll
                for (int i = 0; i < 4; i++) cS[mt][nt][i] = 0.f;
        #pragma unroll
        for (int kk = 0; kk < 4; kk++) {
            int k0 = kk * 16;
            unsigned ah[2][4], al[2][4], bhf[4][2], blf[4][2];
            #pragma unroll
            for (int mt = 0; mt < 2; mt++) {
                int rb = wm0 + mt * 16;
                ah[mt][0] = *reinterpret_cast<const unsigned*>(&Qh[rb + g][k0 + 2*t]);
                ah[mt][1] = *reinterpret_cast<const unsigned*>(&Qh[rb + 8 + g][k0 + 2*t]);
                ah[mt][2] = *reinterpret_cast<const unsigned*>(&Qh[rb + g][k0 + 8 + 2*t]);
                ah[mt][3] = *reinterpret_cast<const unsigned*>(&Qh[rb + 8 + g][k0 + 8 + 2*t]);
                al[mt][0] = *reinterpret_cast<const unsigned*>(&Ql[rb + g][k0 + 2*t]);
                al[mt][1] = *reinterpret_cast<const unsigned*>(&Ql[rb + 8 + g][k0 + 2*t]);
                al[mt][2] = *reinterpret_cast<const unsigned*>(&Ql[rb + g][k0 + 8 + 2*t]);
                al[mt][3] = *reinterpret_cast<const unsigned*>(&Ql[rb + 8 + g][k0 + 8 + 2*t]);
            }
            #pragma unroll
            for (int nt = 0; nt < 4; nt++) {
                int cb = wn0 + nt * 8 + g;
                bhf[nt][0] = *reinterpret_cast<const unsigned*>(&Kh[cb][k0 + 2*t]);
                bhf[nt][1] = *reinterpret_cast<const unsigned*>(&Kh[cb][k0 + 8 + 2*t]);
                blf[nt][0] = *reinterpret_cast<const unsigned*>(&Kl[cb][k0 + 2*t]);
                blf[nt][1] = *reinterpret_cast<const unsigned*>(&Kl[cb][k0 + 8 + 2*t]);
            }
            #pragma unroll
            for (int mt = 0; mt < 2; mt++)
                #pragma unroll
                for (int nt = 0; nt < 4; nt++) {
                    mma16(cS[mt][nt], ah[mt], bhf[nt]);
                    mma16(cS[mt][nt], ah[mt], blf[nt]);
                    mma16(cS[mt][nt], al[mt], bhf[nt]);
                }
        }

        // ---- mask + exp (FMA poly + MUFU split) + write attn + stage tf32 P ----
        #pragma unroll
        for (int mt = 0; mt < 2; mt++)
            #pragma unroll
            for (int nt = 0; nt < 4; nt++) {
                int tloc = wn0 + nt * 8 + 2 * t;
                int tg = T0 + tloc;
                #pragma unroll
                for (int half = 0; half < 2; half++) {
                    int rloc = wm0 + mt * 16 + half * 8 + g;
                    int sg = S0 + rloc;
                    unsigned mw = m2[rloc][tloc >> 5];
                    int sh = tloc & 31;
                    float e0 = fexp8(cS[mt][nt][half * 2]);               // FMA pipe
                    float e1 = __expf(cS[mt][nt][half * 2 + 1] * 0.125f); // MUFU pipe
                    float p0 = ((mw >> sh) & 1u)       ? e0 : 0.f;
                    float p1 = ((mw >> (sh + 1)) & 1u) ? e1 : 0.f;
                    *reinterpret_cast<float2*>(&aout[(size_t)sg * Sn + tg]) = make_float2(p0, p1);
                    *reinterpret_cast<float2*>(&Ps[rloc][tloc]) = make_float2(tf32r(p0), tf32r(p1));
                    rpart[mt][half] += p0 + p1;
                }
            }
        __syncthreads();

        // ---- heads += P @ V (tf32, operands pre-rounded; direct bit loads) ----
        #pragma unroll
        for (int kk = 0; kk < 8; kk++) {
            int k0 = kk * 8;
            unsigned a[2][4], bf[4][2];
            #pragma unroll
            for (int mt = 0; mt < 2; mt++) {
                int rb = wm0 + mt * 16;
                a[mt][0] = __float_as_uint(Ps[rb + g][k0 + t]);
                a[mt][1] = __float_as_uint(Ps[rb + 8 + g][k0 + t]);
                a[mt][2] = __float_as_uint(Ps[rb + g][k0 + t + 4]);
                a[mt][3] = __float_as_uint(Ps[rb + 8 + g][k0 + t + 4]);
            }
            #pragma unroll
            for (int nt = 0; nt < 4; nt++) {
                int cb = wn0 + nt * 8 + g;
                bf[nt][0] = __float_as_uint(Vs[k0 + t][cb]);
                bf[nt][1] = __float_as_uint(Vs[k0 + t + 4][cb]);
            }
            #pragma unroll
            for (int mt = 0; mt < 2; mt++)
                #pragma unroll
                for (int nt = 0; nt < 4; nt++)
                    mma8(cO[mt][nt], a[mt], bf[nt]);
        }
        __syncthreads();
    }

    // ---- rowsum reduce ----
    #pragma unroll
    for (int mt = 0; mt < 2; mt++)
        #pragma unroll
        for (int half = 0; half < 2; half++) {
            float v = rpart[mt][half];
            v += __shfl_xor_sync(0xffffffffu, v, 1);
            v += __shfl_xor_sync(0xffffffffu, v, 2);
            if (t == 0) atomicAdd(&rowsum[wm0 + mt * 16 + half * 8 + g], v);
        }
    __syncthreads();

    // ---- write heads (scaled by 0.25/rowsum) ----
    float* hdst = g_heads + (size_t)bh * Sn * DHn;
    #pragma unroll
    for (int mt = 0; mt < 2; mt++)
        #pragma unroll
        for (int nt = 0; nt < 4; nt++) {
            int e = wn0 + nt * 8 + 2 * t;
            #pragma unroll
            for (int half = 0; half < 2; half++) {
                int rloc = wm0 + mt * 16 + half * 8 + g;
                float inv = 0.25f / rowsum[rloc];
                float2 val = make_float2(cO[mt][nt][half * 2] * inv, cO[mt][nt][half * 2 + 1] * inv);
                *reinterpret_cast<float2*>(&hdst[(size_t)(S0 + rloc) * DHn + e]) = val;
            }
        }
    __syncthreads();

    // ---- in-kernel normalization of this CTA's attn slice (L2-warm) ----
    if (tid < 128) rowsum[tid] = 1.f / rowsum[tid];
    __syncthreads();
    {
        float4* rbase = reinterpret_cast<float4*>(aout + (size_t)S0 * Sn);
        const int NF4 = 128 * (Sn / 4);   // 65536 float4
        for (int i = tid; i < NF4; i += 256) {
            int r = i >> 9;               // Sn/4 = 512 float4 per row
            float inv = rowsum[r];
            float4 vv = rbase[i];
            vv.x *= inv; vv.y *= inv; vv.z *= inv; vv.w *= inv;
            rbase[i] = vv;
        }
    }
}

// ================= Kernel 4: out = mean_h(heads) @ Wo =================
__global__ __launch_bounds__(256) void final_kernel(
    const float* __restrict__ Wo, float* __restrict__ out)
{
    __shared__ float avg[16][64];
    int r0 = blockIdx.x * 16;
    int tid = threadIdx.x;
    #pragma unroll
    for (int it = 0; it < 4; it++) {
        int i = tid + it * 256;
        int rr = i >> 6, e = i & 63;
        int R = r0 + rr;
        int bb = R >> 11, s = R & 2047;
        size_t base = ((size_t)(bb * Hn) * Sn + s) * DHn + e;
        avg[rr][e] = g_heads[base] + g_heads[base + (size_t)Sn * DHn]
                   + g_heads[base + 2 * (size_t)Sn * DHn] + g_heads[base + 3 * (size_t)Sn * DHn];
    }
    __syncthreads();
    float acc[16];
    #pragma unroll
    for (int i = 0; i < 16; i++) acc[i] = 0.f;
    int d = tid;
    #pragma unroll 16
    for (int e = 0; e < 64; e++) {
        float w = Wo[e * Dn + d];
        #pragma unroll
        for (int i = 0; i < 16; i++) acc[i] += avg[i][e] * w;
    }
    #pragma unroll
    for (int i = 0; i < 16; i++) out[(size_t)(r0 + i) * Dn + d] = acc[i];
}

// ================= launch =================
extern "C" void kernel_launch(void* const* d_in, const int* in_sizes, int n_in,
                              void* d_out, int out_size) {
    const float* q    = (const float*)d_in[0];
    const float* k    = (const float*)d_in[1];
    const float* v    = (const float*)d_in[2];
    const int*   mask = (const int*)  d_in[3];
    const float* Wq   = (const float*)d_in[4];
    const float* Wk   = (const float*)d_in[5];
    const float* Wv   = (const float*)d_in[6];
    const float* Wo   = (const float*)d_in[7];
    float* outp  = (float*)d_out;
    float* attnp = outp + (size_t)Bn * Sn * Dn;   // outputs first, attn second

    (void)in_sizes; (void)n_in; (void)out_size;

    cudaFuncSetAttribute(attn_kernel, cudaFuncAttributeMaxDynamicSharedMemorySize, 110080);

    pack_mask_kernel<<<(Bn * Sn * Sn) / 256, 256>>>(mask);
    proj_kernel<<<dim3(4, 128, 3), 256>>>(q, k, v, Wq, Wk, Wv);
    attn_kernel<<<dim3(16, 4, 8), 256, 110080>>>(attnp);
    final_kernel<<<(Bn * Sn) / 16, 256>>>(Wo, outp);
}